// round 12
// baseline (speedup 1.0000x reference)
#include <cuda_runtime.h>
#include <cuda_fp16.h>
#include <cstdint>

#define B_    8
#define S_    4096
#define H_    16
#define NTILES 2048      // (B*H*S)/256
#define TPB   512        // 16 warps, each warp owns 16 rows of the 256-row tile
#define NWARP 16
#define GRID  148
#define EPSf  1e-5f

typedef uint32_t u32;
typedef uint64_t u64;

// ---------------- SMEM layout (bytes) ----------------
// All GEMMs fp16 2-pass: B fragments uint2 {b0h,b1h} per position per lane
#define OFF_WK   0            // 32 pos * 32 lanes * 8B = 8192
#define OFF_WV   8192
#define OFF_WQ   16384
#define OFF_W1   24576        // 64 pos = 16384
#define OFF_W2   40960        // 64 pos = 16384
#define OFF_PRM  57344        // fg[64], l1w[64], l1b[64], b2[64], l2w[128], l2b[128]
#define SMEM_TOTAL (57344 + 512 * 4)

// K-permutation pi (all GEMMs): physical k 16kt+2t+j / 16kt+2t+8+j hold logical
// cols 16kt+4t+j / 16kt+4t+2+j.
// N-perm sigma (G1,G2,G3,G5; N=64):  acc(nt, c0/c1) = logical cols 16(nt&3)+4t+2(nt>>2)+{0,1}
// N-perm sigma2 (G4; N=128):          acc(nt, c0/c1) = logical cols 16(nt&7)+4t+2(nt>>3)+{0,1}

// ---- fp16 split (hi + residual), low half = e ----
__device__ __forceinline__ void split2h(float e, float o, u32 &hi, u32 &lo) {
    u32 h; asm("cvt.rn.f16x2.f32 %0, %1, %2;" : "=r"(h) : "f"(o), "f"(e));
    __half2 hh = *reinterpret_cast<__half2 *>(&h);
    float2 hf = __half22float2(hh);
    float re = e - hf.x, ro = o - hf.y;
    asm("cvt.rn.f16x2.f32 %0, %1, %2;" : "=r"(lo) : "f"(ro), "f"(re));
    hi = h;
}
// fp16 round only (B hi, no residual)
__device__ __forceinline__ u32 pack2h(float e, float o) {
    u32 h; asm("cvt.rn.f16x2.f32 %0, %1, %2;" : "=r"(h) : "f"(o), "f"(e));
    return h;
}

__device__ __forceinline__ void mma16816h(float *c, const u32 *a, u32 b0, u32 b1) {
    asm volatile("mma.sync.aligned.m16n8k16.row.col.f32.f16.f16.f32 "
                 "{%0,%1,%2,%3}, {%4,%5,%6,%7}, {%8,%9}, {%0,%1,%2,%3};"
                 : "+f"(c[0]), "+f"(c[1]), "+f"(c[2]), "+f"(c[3])
                 : "r"(a[0]), "r"(a[1]), "r"(a[2]), "r"(a[3]), "r"(b0), "r"(b1));
}

// fp16 2-pass GEMM, RAW-chain-broken: per kt, process nt in batches of 8.
// Batch: 8 independent LDS.64 (MLP=8), 8 ah-pass MMAs (distinct accumulators),
// then 8 al-pass MMAs (RAW distance 8).
template<int NT, int KT>
__device__ __forceinline__ void do_gemm_h(float (*c)[4], const u32 *ah, const u32 *al,
                                          const uint2 *Bsm, int lane) {
    static_assert(NT % 8 == 0 || NT == 8, "NT multiple of 8");
#pragma unroll
    for (int kt = 0; kt < KT; kt++) {
#pragma unroll
        for (int nb = 0; nb < NT; nb += 8) {
            uint2 p[8];
#pragma unroll
            for (int j = 0; j < 8; j++)
                p[j] = Bsm[((nb + j) * KT + kt) * 32 + lane];
#pragma unroll
            for (int j = 0; j < 8; j++)
                mma16816h(c[nb + j], ah + 4*kt, p[j].x, p[j].y);
#pragma unroll
            for (int j = 0; j < 8; j++)
                mma16816h(c[nb + j], al + 4*kt, p[j].x, p[j].y);
        }
    }
}

// Row index under N-permutation (sigma for NT==8, sigma2 for NT==16)
__device__ __forceinline__ int permrow(int nt, int g, int NT, bool perm) {
    if (!perm) return nt * 8 + g;
    int mask = (NT == 8) ? 3 : 7;
    int hi   = (NT == 8) ? (nt >> 2) : (nt >> 3);
    return ((nt & mask) << 4) + ((g >> 1) << 2) + (hi << 1) + (g & 1);
}

// Stage fp16-hi B fragments (uint2), K read through pi
template<bool PERM>
__device__ __forceinline__ void stageBh(uint2 *dst, const float * __restrict__ W,
                                        int NT, int KT, int K, int wid, int lane) {
    const int g = lane >> 2, t = lane & 3;
#pragma unroll 1
    for (int m = wid; m < NT * KT; m += NWARP) {
        int nt = m / KT, kt = m - nt * KT;
        int row = permrow(nt, g, NT, PERM);
        float4 wv = *(const float4 *)(W + row * K + kt * 16 + 4 * t);
        uint2 v = { pack2h(wv.x, wv.y), pack2h(wv.z, wv.w) };
        dst[m * 32 + lane] = v;
    }
}

// A kt-step load under pi, fp16 split
__device__ __forceinline__ void loadA_kt_h(const float * __restrict__ r0,
                                           const float * __restrict__ r1,
                                           int t, u32 *ah, u32 *al) {
    float4 w0 = *(const float4 *)(r0 + 4 * t);
    float4 w1 = *(const float4 *)(r1 + 4 * t);
    split2h(w0.x, w0.y, ah[0], al[0]);
    split2h(w1.x, w1.y, ah[1], al[1]);
    split2h(w0.z, w0.w, ah[2], al[2]);
    split2h(w1.z, w1.w, ah[3], al[3]);
}

__device__ __forceinline__ float qreduce(float v) {
    v += __shfl_xor_sync(0xffffffffu, v, 1);
    v += __shfl_xor_sync(0xffffffffu, v, 2);
    return v;
}

__device__ __forceinline__ int qoff_of(int row) {
    int s = row & (S_ - 1);
    int h = (row >> 12) & (H_ - 1);
    int b = row >> 16;
    return (((b << 12) | s) << 10) + (h << 6);
}

__device__ __forceinline__ float gatef(float fg, float m, float kp, float vp) {
    float fgm  = fg * m;
    float cell = fmaf(kp, vp, fgm);
    return fmaf(1.f - fg, cell, fgm);
}

extern __shared__ char smem[];

__global__ void __launch_bounds__(TPB, 1) mhba_hmma_kernel(
    const float* __restrict__ Qin, const float* __restrict__ Kin,
    const float* __restrict__ Vin, const float* __restrict__ MEM,
    const float* __restrict__ Wq,  const float* __restrict__ Wk,
    const float* __restrict__ Wv,  const float* __restrict__ FG,
    const float* __restrict__ LN1W, const float* __restrict__ LN1B,
    const float* __restrict__ W1,
    const float* __restrict__ LN2W, const float* __restrict__ LN2B,
    const float* __restrict__ W2,  const float* __restrict__ B2,
    float* __restrict__ OUT, float* __restrict__ CM)
{
    const int tid  = threadIdx.x;
    const int wid  = tid >> 5;
    const int lane = tid & 31;
    const int g = lane >> 2, t = lane & 3;

    float *pf = (float *)(smem + OFF_PRM);
    if (tid < 64) {
        pf[tid]       = FG[tid];
        pf[64 + tid]  = LN1W[tid];
        pf[128 + tid] = LN1B[tid];
        pf[192 + tid] = B2[tid];
    }
    if (tid < 128) {
        pf[256 + tid] = LN2W[tid];
        pf[384 + tid] = LN2B[tid];
    }
    stageBh<true>((uint2 *)(smem + OFF_WK), Wk, 8,  4, 64,  wid, lane);
    stageBh<true>((uint2 *)(smem + OFF_WV), Wv, 8,  4, 64,  wid, lane);
    stageBh<true>((uint2 *)(smem + OFF_WQ), Wq, 8,  4, 64,  wid, lane);
    stageBh<true>((uint2 *)(smem + OFF_W1), W1, 16, 4, 64,  wid, lane);
    stageBh<true>((uint2 *)(smem + OFF_W2), W2, 8,  8, 128, wid, lane);
    __syncthreads();

    const uint2 *BWk = (const uint2 *)(smem + OFF_WK);
    const uint2 *BWv = (const uint2 *)(smem + OFF_WV);
    const uint2 *BWq = (const uint2 *)(smem + OFF_WQ);
    const uint2 *BW1 = (const uint2 *)(smem + OFF_W1);
    const uint2 *BW2 = (const uint2 *)(smem + OFF_W2);

#pragma unroll 1
    for (int tile = blockIdx.x; tile < NTILES; tile += gridDim.x) {
        const int rbase = tile * 256 + wid * 16;
        const int row0 = rbase + g;
        const int row1 = row0 + 8;
        const int q0 = qoff_of(row0), q1 = qoff_of(row1);
        const int m0 = row0 << 6,     m1 = row1 << 6;

        u32 ah[16], al[16];

        // ---------- GEMM1: kp = Xk @ Wk^T ----------
#pragma unroll
        for (int kt = 0; kt < 4; kt++)
            loadA_kt_h(Kin + q0 + kt * 16, Kin + q1 + kt * 16, t, ah + 4 * kt, al + 4 * kt);
        float ckp[8][4];
#pragma unroll
        for (int i = 0; i < 8; i++) { ckp[i][0]=0.f; ckp[i][1]=0.f; ckp[i][2]=0.f; ckp[i][3]=0.f; }
        do_gemm_h<8, 4>(ckp, ah, al, BWk, lane);

        // ---------- GEMM2: vp = Xv @ Wv^T ----------
#pragma unroll
        for (int kt = 0; kt < 4; kt++)
            loadA_kt_h(Vin + q0 + kt * 16, Vin + q1 + kt * 16, t, ah + 4 * kt, al + 4 * kt);
        float cvp[8][4];
#pragma unroll
        for (int i = 0; i < 8; i++) { cvp[i][0]=0.f; cvp[i][1]=0.f; cvp[i][2]=0.f; cvp[i][3]=0.f; }
        do_gemm_h<8, 4>(cvp, ah, al, BWv, lane);

        // ---------- gate -> cur_mem (float4 stores via nt/nt+4 pairing) ----------
#pragma unroll
        for (int nt = 0; nt < 4; nt++) {
            const int colb4 = (nt << 4) + 4 * t;    // 16nt + 4t: 4 contiguous cols
            float4 fg4 = *(const float4 *)(pf + colb4);
            float4 mA4 = *(const float4 *)(MEM + m0 + colb4);
            float4 mB4 = *(const float4 *)(MEM + m1 + colb4);
            float4 cA, cB;
            cA.x = gatef(fg4.x, mA4.x, ckp[nt][0],   cvp[nt][0]);
            cA.y = gatef(fg4.y, mA4.y, ckp[nt][1],   cvp[nt][1]);
            cA.z = gatef(fg4.z, mA4.z, ckp[nt+4][0], cvp[nt+4][0]);
            cA.w = gatef(fg4.w, mA4.w, ckp[nt+4][1], cvp[nt+4][1]);
            cB.x = gatef(fg4.x, mB4.x, ckp[nt][2],   cvp[nt][2]);
            cB.y = gatef(fg4.y, mB4.y, ckp[nt][3],   cvp[nt][3]);
            cB.z = gatef(fg4.z, mB4.z, ckp[nt+4][2], cvp[nt+4][2]);
            cB.w = gatef(fg4.w, mB4.w, ckp[nt+4][3], cvp[nt+4][3]);
            *(float4 *)(CM + m0 + colb4) = cA;
            *(float4 *)(CM + m1 + colb4) = cB;
            cvp[nt][0]   = cA.x; cvp[nt][1]   = cA.y;
            cvp[nt+4][0] = cA.z; cvp[nt+4][1] = cA.w;
            cvp[nt][2]   = cB.x; cvp[nt][3]   = cB.y;
            cvp[nt+4][2] = cB.z; cvp[nt+4][3] = cB.w;
        }

        // ---------- GEMM3: qp = Xq @ Wq^T ----------
#pragma unroll
        for (int kt = 0; kt < 4; kt++)
            loadA_kt_h(Qin + q0 + kt * 16, Qin + q1 + kt * 16, t, ah + 4 * kt, al + 4 * kt);
#pragma unroll
        for (int i = 0; i < 8; i++) { ckp[i][0]=0.f; ckp[i][1]=0.f; ckp[i][2]=0.f; ckp[i][3]=0.f; }
        do_gemm_h<8, 4>(ckp, ah, al, BWq, lane);

        // ---------- cv = qp * cm ; LN1 (float4 param reads) ----------
#pragma unroll
        for (int nt = 0; nt < 8; nt++) {
            cvp[nt][0] *= ckp[nt][0]; cvp[nt][1] *= ckp[nt][1];
            cvp[nt][2] *= ckp[nt][2]; cvp[nt][3] *= ckp[nt][3];
        }
        {
            float s0 = 0.f, sq0 = 0.f, s1 = 0.f, sq1 = 0.f;
#pragma unroll
            for (int nt = 0; nt < 8; nt++) {
                s0 += cvp[nt][0] + cvp[nt][1];
                sq0 = fmaf(cvp[nt][0], cvp[nt][0], fmaf(cvp[nt][1], cvp[nt][1], sq0));
                s1 += cvp[nt][2] + cvp[nt][3];
                sq1 = fmaf(cvp[nt][2], cvp[nt][2], fmaf(cvp[nt][3], cvp[nt][3], sq1));
            }
            s0 = qreduce(s0); sq0 = qreduce(sq0);
            s1 = qreduce(s1); sq1 = qreduce(sq1);
            float mu0 = s0 * (1.f / 64.f);
            float rs0 = rsqrtf(sq0 * (1.f / 64.f) - mu0 * mu0 + EPSf);
            float mu1 = s1 * (1.f / 64.f);
            float rs1 = rsqrtf(sq1 * (1.f / 64.f) - mu1 * mu1 + EPSf);
#pragma unroll
            for (int nt = 0; nt < 4; nt++) {
                const int colb4 = (nt << 4) + 4 * t;
                float4 w  = *(const float4 *)(pf + 64 + colb4);
                float4 bb = *(const float4 *)(pf + 128 + colb4);
                cvp[nt][0]   = fmaf((cvp[nt][0]   - mu0) * rs0, w.x, bb.x);
                cvp[nt][1]   = fmaf((cvp[nt][1]   - mu0) * rs0, w.y, bb.y);
                cvp[nt+4][0] = fmaf((cvp[nt+4][0] - mu0) * rs0, w.z, bb.z);
                cvp[nt+4][1] = fmaf((cvp[nt+4][1] - mu0) * rs0, w.w, bb.w);
                cvp[nt][2]   = fmaf((cvp[nt][2]   - mu1) * rs1, w.x, bb.x);
                cvp[nt][3]   = fmaf((cvp[nt][3]   - mu1) * rs1, w.y, bb.y);
                cvp[nt+4][2] = fmaf((cvp[nt+4][2] - mu1) * rs1, w.z, bb.z);
                cvp[nt+4][3] = fmaf((cvp[nt+4][3] - mu1) * rs1, w.w, bb.w);
            }
        }
        // repack ln1(cv) -> pi-ordered fp16 A frags (K=64): kt <- nt=kt (lo), nt=kt+4 (hi)
#pragma unroll
        for (int kt = 0; kt < 4; kt++) {
            split2h(cvp[kt][0],   cvp[kt][1],   ah[4*kt+0], al[4*kt+0]);
            split2h(cvp[kt][2],   cvp[kt][3],   ah[4*kt+1], al[4*kt+1]);
            split2h(cvp[kt+4][0], cvp[kt+4][1], ah[4*kt+2], al[4*kt+2]);
            split2h(cvp[kt+4][2], cvp[kt+4][3], ah[4*kt+3], al[4*kt+3]);
        }

        // ---------- GEMM4: h1 = ln1cv @ W1^T (N=128, sigma2 rows) ----------
        float h1[16][4];
#pragma unroll
        for (int i = 0; i < 16; i++) { h1[i][0]=0.f; h1[i][1]=0.f; h1[i][2]=0.f; h1[i][3]=0.f; }
        do_gemm_h<16, 4>(h1, ah, al, BW1, lane);

        // ---------- LN2 (float4 params via nt/nt+8 pairing) ----------
        {
            float s0 = 0.f, sq0 = 0.f, s1 = 0.f, sq1 = 0.f;
#pragma unroll
            for (int nt = 0; nt < 16; nt++) {
                s0 += h1[nt][0] + h1[nt][1];
                sq0 = fmaf(h1[nt][0], h1[nt][0], fmaf(h1[nt][1], h1[nt][1], sq0));
                s1 += h1[nt][2] + h1[nt][3];
                sq1 = fmaf(h1[nt][2], h1[nt][2], fmaf(h1[nt][3], h1[nt][3], sq1));
            }
            s0 = qreduce(s0); sq0 = qreduce(sq0);
            s1 = qreduce(s1); sq1 = qreduce(sq1);
            float mu0 = s0 * (1.f / 128.f);
            float rs0 = rsqrtf(sq0 * (1.f / 128.f) - mu0 * mu0 + EPSf);
            float mu1 = s1 * (1.f / 128.f);
            float rs1 = rsqrtf(sq1 * (1.f / 128.f) - mu1 * mu1 + EPSf);
#pragma unroll
            for (int nt = 0; nt < 8; nt++) {
                const int colb4 = (nt << 4) + 4 * t;
                float4 w  = *(const float4 *)(pf + 256 + colb4);
                float4 bb = *(const float4 *)(pf + 384 + colb4);
                h1[nt][0]   = fmaf((h1[nt][0]   - mu0) * rs0, w.x, bb.x);
                h1[nt][1]   = fmaf((h1[nt][1]   - mu0) * rs0, w.y, bb.y);
                h1[nt+8][0] = fmaf((h1[nt+8][0] - mu0) * rs0, w.z, bb.z);
                h1[nt+8][1] = fmaf((h1[nt+8][1] - mu0) * rs0, w.w, bb.w);
                h1[nt][2]   = fmaf((h1[nt][2]   - mu1) * rs1, w.x, bb.x);
                h1[nt][3]   = fmaf((h1[nt][3]   - mu1) * rs1, w.y, bb.y);
                h1[nt+8][2] = fmaf((h1[nt+8][2] - mu1) * rs1, w.z, bb.z);
                h1[nt+8][3] = fmaf((h1[nt+8][3] - mu1) * rs1, w.w, bb.w);
            }
        }
        // repack ln2(h1) -> pi-ordered fp16 A frags (K=128): kt <- nt=kt (lo), nt=kt+8 (hi)
        u32 ah2[32], al2[32];
#pragma unroll
        for (int kt = 0; kt < 8; kt++) {
            split2h(h1[kt][0],   h1[kt][1],   ah2[4*kt+0], al2[4*kt+0]);
            split2h(h1[kt][2],   h1[kt][3],   ah2[4*kt+1], al2[4*kt+1]);
            split2h(h1[kt+8][0], h1[kt+8][1], ah2[4*kt+2], al2[4*kt+2]);
            split2h(h1[kt+8][2], h1[kt+8][3], ah2[4*kt+3], al2[4*kt+3]);
        }

        // ---------- GEMM5: out = ln2h1 @ W2^T + b2 (sigma rows; float4 stores) ----------
        float co[8][4];
#pragma unroll
        for (int i = 0; i < 8; i++) { co[i][0]=0.f; co[i][1]=0.f; co[i][2]=0.f; co[i][3]=0.f; }
        do_gemm_h<8, 8>(co, ah2, al2, BW2, lane);

#pragma unroll
        for (int nt = 0; nt < 4; nt++) {
            const int colb4 = (nt << 4) + 4 * t;
            float4 b4 = *(const float4 *)(pf + 192 + colb4);
            float4 oA, oB;
            oA.x = co[nt][0]   + b4.x; oA.y = co[nt][1]   + b4.y;
            oA.z = co[nt+4][0] + b4.z; oA.w = co[nt+4][1] + b4.w;
            oB.x = co[nt][2]   + b4.x; oB.y = co[nt][3]   + b4.y;
            oB.z = co[nt+4][2] + b4.z; oB.w = co[nt+4][3] + b4.w;
            *(float4 *)(OUT + q0 + colb4) = oA;
            *(float4 *)(OUT + q1 + colb4) = oB;
        }
    }
}

extern "C" void kernel_launch(void* const* d_in, const int* in_sizes, int n_in,
                              void* d_out, int out_size) {
    const float* Qin  = (const float*)d_in[0];
    const float* Kin  = (const float*)d_in[1];
    const float* Vin  = (const float*)d_in[2];
    const float* MEM  = (const float*)d_in[3];
    const float* Wq   = (const float*)d_in[4];
    const float* Wk   = (const float*)d_in[5];
    const float* Wv   = (const float*)d_in[6];
    const float* FG   = (const float*)d_in[7];
    const float* LN1W = (const float*)d_in[8];
    const float* LN1B = (const float*)d_in[9];
    const float* W1   = (const float*)d_in[10];
    const float* LN2W = (const float*)d_in[11];
    const float* LN2B = (const float*)d_in[12];
    const float* W2   = (const float*)d_in[13];
    const float* B2   = (const float*)d_in[14];

    float* OUT = (float*)d_out;                       // [B,S,HID]
    float* CM  = OUT + (size_t)B_ * S_ * H_ * 64;     // [B,H,S,D]

    static int attr_set = 0;
    if (!attr_set) {
        cudaFuncSetAttribute(mhba_hmma_kernel,
                             cudaFuncAttributeMaxDynamicSharedMemorySize, SMEM_TOTAL);
        attr_set = 1;
    }

    mhba_hmma_kernel<<<GRID, TPB, SMEM_TOTAL>>>(
        Qin, Kin, Vin, MEM, Wq, Wk, Wv, FG,
        LN1W, LN1B, W1, LN2W, LN2B, W2, B2, OUT, CM);
}

// round 13
// speedup vs baseline: 1.0668x; 1.0668x over previous
#include <cuda_runtime.h>
#include <cuda_fp16.h>
#include <cstdint>

#define B_    8
#define S_    4096
#define H_    16
#define NTILES 2048      // (B*H*S)/256
#define TPB   512        // 16 warps, each warp owns 16 rows of the 256-row tile
#define NWARP 16
#define GRID  148
#define EPSf  1e-5f

typedef uint32_t u32;
typedef uint64_t u64;

// ---------------- SMEM layout (bytes) ----------------
// All GEMMs fp16: B fragments uint2 {b0h,b1h} per position per lane
#define OFF_WK   0            // 32 pos * 32 lanes * 8B = 8192
#define OFF_WV   8192
#define OFF_WQ   16384
#define OFF_W1   24576        // 64 pos = 16384
#define OFF_W2   40960        // 64 pos = 16384
#define OFF_PRM  57344        // fg[64], l1w[64], l1b[64], b2[64], l2w[128], l2b[128]
#define SMEM_TOTAL (57344 + 512 * 4)

// K-permutation pi (all GEMMs): physical k 16kt+2t+j / 16kt+2t+8+j hold logical
// cols 16kt+4t+j / 16kt+4t+2+j.
// N-perm sigma (G1,G2,G3,G5; N=64):  acc(nt, c0/c1) = logical cols 16(nt&3)+4t+2(nt>>2)+{0,1}
// N-perm sigma2 (G4; N=128):          acc(nt, c0/c1) = logical cols 16(nt&7)+4t+2(nt>>3)+{0,1}
// Precision: G1/G2 pure fp16 (1-pass); G3/G4/G5 fp16 2-pass (A hi+residual).

// ---- fp16 split (hi + residual), low half = e ----
__device__ __forceinline__ void split2h(float e, float o, u32 &hi, u32 &lo) {
    u32 h; asm("cvt.rn.f16x2.f32 %0, %1, %2;" : "=r"(h) : "f"(o), "f"(e));
    __half2 hh = *reinterpret_cast<__half2 *>(&h);
    float2 hf = __half22float2(hh);
    float re = e - hf.x, ro = o - hf.y;
    asm("cvt.rn.f16x2.f32 %0, %1, %2;" : "=r"(lo) : "f"(ro), "f"(re));
    hi = h;
}
// fp16 round only
__device__ __forceinline__ u32 pack2h(float e, float o) {
    u32 h; asm("cvt.rn.f16x2.f32 %0, %1, %2;" : "=r"(h) : "f"(o), "f"(e));
    return h;
}

__device__ __forceinline__ void mma16816h(float *c, const u32 *a, u32 b0, u32 b1) {
    asm volatile("mma.sync.aligned.m16n8k16.row.col.f32.f16.f16.f32 "
                 "{%0,%1,%2,%3}, {%4,%5,%6,%7}, {%8,%9}, {%0,%1,%2,%3};"
                 : "+f"(c[0]), "+f"(c[1]), "+f"(c[2]), "+f"(c[3])
                 : "r"(a[0]), "r"(a[1]), "r"(a[2]), "r"(a[3]), "r"(b0), "r"(b1));
}

// fp16 2-pass GEMM (A hi + residual)
template<int NT, int KT>
__device__ __forceinline__ void do_gemm_h(float (*c)[4], const u32 *ah, const u32 *al,
                                          const uint2 *Bsm, int lane) {
#pragma unroll
    for (int kt = 0; kt < KT; kt++) {
#pragma unroll
        for (int nt = 0; nt < NT; nt++) {
            const int m = nt * KT + kt;
            uint2 p = Bsm[m * 32 + lane];
            mma16816h(c[nt], ah + 4*kt, p.x, p.y);
            mma16816h(c[nt], al + 4*kt, p.x, p.y);
        }
    }
}
// fp16 1-pass GEMM (A rounded only)
template<int NT, int KT>
__device__ __forceinline__ void do_gemm_h1(float (*c)[4], const u32 *ah,
                                           const uint2 *Bsm, int lane) {
#pragma unroll
    for (int kt = 0; kt < KT; kt++) {
#pragma unroll
        for (int nt = 0; nt < NT; nt++) {
            const int m = nt * KT + kt;
            uint2 p = Bsm[m * 32 + lane];
            mma16816h(c[nt], ah + 4*kt, p.x, p.y);
        }
    }
}

// Row index under N-permutation (sigma for NT==8, sigma2 for NT==16)
__device__ __forceinline__ int permrow(int nt, int g, int NT, bool perm) {
    if (!perm) return nt * 8 + g;
    int mask = (NT == 8) ? 3 : 7;
    int hi   = (NT == 8) ? (nt >> 2) : (nt >> 3);
    return ((nt & mask) << 4) + ((g >> 1) << 2) + (hi << 1) + (g & 1);
}

// Stage fp16-hi B fragments (uint2), K read through pi
template<bool PERM>
__device__ __forceinline__ void stageBh(uint2 *dst, const float * __restrict__ W,
                                        int NT, int KT, int K, int wid, int lane) {
    const int g = lane >> 2, t = lane & 3;
#pragma unroll 1
    for (int m = wid; m < NT * KT; m += NWARP) {
        int nt = m / KT, kt = m - nt * KT;
        int row = permrow(nt, g, NT, PERM);
        float4 wv = *(const float4 *)(W + row * K + kt * 16 + 4 * t);
        uint2 v = { pack2h(wv.x, wv.y), pack2h(wv.z, wv.w) };
        dst[m * 32 + lane] = v;
    }
}

// A kt-step load under pi, fp16 2-pass split
__device__ __forceinline__ void loadA_kt_h(const float * __restrict__ r0,
                                           const float * __restrict__ r1,
                                           int t, u32 *ah, u32 *al) {
    float4 w0 = *(const float4 *)(r0 + 4 * t);
    float4 w1 = *(const float4 *)(r1 + 4 * t);
    split2h(w0.x, w0.y, ah[0], al[0]);
    split2h(w1.x, w1.y, ah[1], al[1]);
    split2h(w0.z, w0.w, ah[2], al[2]);
    split2h(w1.z, w1.w, ah[3], al[3]);
}
// A kt-step load under pi, fp16 round-only (1-pass)
__device__ __forceinline__ void loadA_kt_h1(const float * __restrict__ r0,
                                            const float * __restrict__ r1,
                                            int t, u32 *ah) {
    float4 w0 = *(const float4 *)(r0 + 4 * t);
    float4 w1 = *(const float4 *)(r1 + 4 * t);
    ah[0] = pack2h(w0.x, w0.y);
    ah[1] = pack2h(w1.x, w1.y);
    ah[2] = pack2h(w0.z, w0.w);
    ah[3] = pack2h(w1.z, w1.w);
}

__device__ __forceinline__ float qreduce(float v) {
    v += __shfl_xor_sync(0xffffffffu, v, 1);
    v += __shfl_xor_sync(0xffffffffu, v, 2);
    return v;
}

__device__ __forceinline__ int qoff_of(int row) {
    int s = row & (S_ - 1);
    int h = (row >> 12) & (H_ - 1);
    int b = row >> 16;
    return (((b << 12) | s) << 10) + (h << 6);
}

__device__ __forceinline__ float gatef(float fg, float m, float kp, float vp) {
    float fgm  = fg * m;
    float cell = fmaf(kp, vp, fgm);
    return fmaf(1.f - fg, cell, fgm);
}

extern __shared__ char smem[];

__global__ void __launch_bounds__(TPB, 1) mhba_hmma_kernel(
    const float* __restrict__ Qin, const float* __restrict__ Kin,
    const float* __restrict__ Vin, const float* __restrict__ MEM,
    const float* __restrict__ Wq,  const float* __restrict__ Wk,
    const float* __restrict__ Wv,  const float* __restrict__ FG,
    const float* __restrict__ LN1W, const float* __restrict__ LN1B,
    const float* __restrict__ W1,
    const float* __restrict__ LN2W, const float* __restrict__ LN2B,
    const float* __restrict__ W2,  const float* __restrict__ B2,
    float* __restrict__ OUT, float* __restrict__ CM)
{
    const int tid  = threadIdx.x;
    const int wid  = tid >> 5;
    const int lane = tid & 31;
    const int g = lane >> 2, t = lane & 3;

    float *pf = (float *)(smem + OFF_PRM);
    if (tid < 64) {
        pf[tid]       = FG[tid];
        pf[64 + tid]  = LN1W[tid];
        pf[128 + tid] = LN1B[tid];
        pf[192 + tid] = B2[tid];
    }
    if (tid < 128) {
        pf[256 + tid] = LN2W[tid];
        pf[384 + tid] = LN2B[tid];
    }
    stageBh<true>((uint2 *)(smem + OFF_WK), Wk, 8,  4, 64,  wid, lane);
    stageBh<true>((uint2 *)(smem + OFF_WV), Wv, 8,  4, 64,  wid, lane);
    stageBh<true>((uint2 *)(smem + OFF_WQ), Wq, 8,  4, 64,  wid, lane);
    stageBh<true>((uint2 *)(smem + OFF_W1), W1, 16, 4, 64,  wid, lane);
    stageBh<true>((uint2 *)(smem + OFF_W2), W2, 8,  8, 128, wid, lane);
    __syncthreads();

    const uint2 *BWk = (const uint2 *)(smem + OFF_WK);
    const uint2 *BWv = (const uint2 *)(smem + OFF_WV);
    const uint2 *BWq = (const uint2 *)(smem + OFF_WQ);
    const uint2 *BW1 = (const uint2 *)(smem + OFF_W1);
    const uint2 *BW2 = (const uint2 *)(smem + OFF_W2);

#pragma unroll 1
    for (int tile = blockIdx.x; tile < NTILES; tile += gridDim.x) {
        const int rbase = tile * 256 + wid * 16;
        const int row0 = rbase + g;
        const int row1 = row0 + 8;
        const int q0 = qoff_of(row0), q1 = qoff_of(row1);
        const int m0 = row0 << 6,     m1 = row1 << 6;

        // ---------- front: K and V fragments up front (independent LDGs) ----------
        u32 kah[16], vah[16];
#pragma unroll
        for (int kt = 0; kt < 4; kt++)
            loadA_kt_h1(Kin + q0 + kt * 16, Kin + q1 + kt * 16, t, kah + 4 * kt);
#pragma unroll
        for (int kt = 0; kt < 4; kt++)
            loadA_kt_h1(Vin + q0 + kt * 16, Vin + q1 + kt * 16, t, vah + 4 * kt);

        // ---------- GEMM1: kp = Xk @ Wk^T (1-pass fp16) ----------
        float ckp[8][4];
#pragma unroll
        for (int i = 0; i < 8; i++) { ckp[i][0]=0.f; ckp[i][1]=0.f; ckp[i][2]=0.f; ckp[i][3]=0.f; }
        do_gemm_h1<8, 4>(ckp, kah, BWk, lane);

        // issue MEM loads now; latency hides under GEMM2
        float4 mmA[4], mmB[4];
#pragma unroll
        for (int nt = 0; nt < 4; nt++) {
            const int colb4 = (nt << 4) + 4 * t;
            mmA[nt] = *(const float4 *)(MEM + m0 + colb4);
            mmB[nt] = *(const float4 *)(MEM + m1 + colb4);
        }

        // ---------- GEMM2: vp = Xv @ Wv^T (1-pass fp16) ----------
        float cvp[8][4];
#pragma unroll
        for (int i = 0; i < 8; i++) { cvp[i][0]=0.f; cvp[i][1]=0.f; cvp[i][2]=0.f; cvp[i][3]=0.f; }
        do_gemm_h1<8, 4>(cvp, vah, BWv, lane);

        // ---------- gate -> cur_mem (float4 stores via nt/nt+4 pairing) ----------
#pragma unroll
        for (int nt = 0; nt < 4; nt++) {
            const int colb4 = (nt << 4) + 4 * t;
            float4 fg4 = *(const float4 *)(pf + colb4);
            float4 cA, cB;
            cA.x = gatef(fg4.x, mmA[nt].x, ckp[nt][0],   cvp[nt][0]);
            cA.y = gatef(fg4.y, mmA[nt].y, ckp[nt][1],   cvp[nt][1]);
            cA.z = gatef(fg4.z, mmA[nt].z, ckp[nt+4][0], cvp[nt+4][0]);
            cA.w = gatef(fg4.w, mmA[nt].w, ckp[nt+4][1], cvp[nt+4][1]);
            cB.x = gatef(fg4.x, mmB[nt].x, ckp[nt][2],   cvp[nt][2]);
            cB.y = gatef(fg4.y, mmB[nt].y, ckp[nt][3],   cvp[nt][3]);
            cB.z = gatef(fg4.z, mmB[nt].z, ckp[nt+4][2], cvp[nt+4][2]);
            cB.w = gatef(fg4.w, mmB[nt].w, ckp[nt+4][3], cvp[nt+4][3]);
            *(float4 *)(CM + m0 + colb4) = cA;
            *(float4 *)(CM + m1 + colb4) = cB;
            cvp[nt][0]   = cA.x; cvp[nt][1]   = cA.y;
            cvp[nt+4][0] = cA.z; cvp[nt+4][1] = cA.w;
            cvp[nt][2]   = cB.x; cvp[nt][3]   = cB.y;
            cvp[nt+4][2] = cB.z; cvp[nt+4][3] = cB.w;
        }

        // ---------- GEMM3: qp = Xq @ Wq^T (2-pass fp16) ----------
        u32 ah[16], al[16];
#pragma unroll
        for (int kt = 0; kt < 4; kt++)
            loadA_kt_h(Qin + q0 + kt * 16, Qin + q1 + kt * 16, t, ah + 4 * kt, al + 4 * kt);
#pragma unroll
        for (int i = 0; i < 8; i++) { ckp[i][0]=0.f; ckp[i][1]=0.f; ckp[i][2]=0.f; ckp[i][3]=0.f; }
        do_gemm_h<8, 4>(ckp, ah, al, BWq, lane);

        // ---------- cv = qp * cm ; LN1 (float4 param reads) ----------
#pragma unroll
        for (int nt = 0; nt < 8; nt++) {
            cvp[nt][0] *= ckp[nt][0]; cvp[nt][1] *= ckp[nt][1];
            cvp[nt][2] *= ckp[nt][2]; cvp[nt][3] *= ckp[nt][3];
        }
        {
            float s0 = 0.f, sq0 = 0.f, s1 = 0.f, sq1 = 0.f;
#pragma unroll
            for (int nt = 0; nt < 8; nt++) {
                s0 += cvp[nt][0] + cvp[nt][1];
                sq0 = fmaf(cvp[nt][0], cvp[nt][0], fmaf(cvp[nt][1], cvp[nt][1], sq0));
                s1 += cvp[nt][2] + cvp[nt][3];
                sq1 = fmaf(cvp[nt][2], cvp[nt][2], fmaf(cvp[nt][3], cvp[nt][3], sq1));
            }
            s0 = qreduce(s0); sq0 = qreduce(sq0);
            s1 = qreduce(s1); sq1 = qreduce(sq1);
            float mu0 = s0 * (1.f / 64.f);
            float rs0 = rsqrtf(sq0 * (1.f / 64.f) - mu0 * mu0 + EPSf);
            float mu1 = s1 * (1.f / 64.f);
            float rs1 = rsqrtf(sq1 * (1.f / 64.f) - mu1 * mu1 + EPSf);
#pragma unroll
            for (int nt = 0; nt < 4; nt++) {
                const int colb4 = (nt << 4) + 4 * t;
                float4 w  = *(const float4 *)(pf + 64 + colb4);
                float4 bb = *(const float4 *)(pf + 128 + colb4);
                cvp[nt][0]   = fmaf((cvp[nt][0]   - mu0) * rs0, w.x, bb.x);
                cvp[nt][1]   = fmaf((cvp[nt][1]   - mu0) * rs0, w.y, bb.y);
                cvp[nt+4][0] = fmaf((cvp[nt+4][0] - mu0) * rs0, w.z, bb.z);
                cvp[nt+4][1] = fmaf((cvp[nt+4][1] - mu0) * rs0, w.w, bb.w);
                cvp[nt][2]   = fmaf((cvp[nt][2]   - mu1) * rs1, w.x, bb.x);
                cvp[nt][3]   = fmaf((cvp[nt][3]   - mu1) * rs1, w.y, bb.y);
                cvp[nt+4][2] = fmaf((cvp[nt+4][2] - mu1) * rs1, w.z, bb.z);
                cvp[nt+4][3] = fmaf((cvp[nt+4][3] - mu1) * rs1, w.w, bb.w);
            }
        }
        // repack ln1(cv) -> pi-ordered fp16 A frags (K=64)
#pragma unroll
        for (int kt = 0; kt < 4; kt++) {
            split2h(cvp[kt][0],   cvp[kt][1],   ah[4*kt+0], al[4*kt+0]);
            split2h(cvp[kt][2],   cvp[kt][3],   ah[4*kt+1], al[4*kt+1]);
            split2h(cvp[kt+4][0], cvp[kt+4][1], ah[4*kt+2], al[4*kt+2]);
            split2h(cvp[kt+4][2], cvp[kt+4][3], ah[4*kt+3], al[4*kt+3]);
        }

        // ---------- GEMM4: h1 = ln1cv @ W1^T (N=128, sigma2 rows, 2-pass) ----------
        float h1[16][4];
#pragma unroll
        for (int i = 0; i < 16; i++) { h1[i][0]=0.f; h1[i][1]=0.f; h1[i][2]=0.f; h1[i][3]=0.f; }
        do_gemm_h<16, 4>(h1, ah, al, BW1, lane);

        // ---------- LN2 (float4 params via nt/nt+8 pairing) ----------
        {
            float s0 = 0.f, sq0 = 0.f, s1 = 0.f, sq1 = 0.f;
#pragma unroll
            for (int nt = 0; nt < 16; nt++) {
                s0 += h1[nt][0] + h1[nt][1];
                sq0 = fmaf(h1[nt][0], h1[nt][0], fmaf(h1[nt][1], h1[nt][1], sq0));
                s1 += h1[nt][2] + h1[nt][3];
                sq1 = fmaf(h1[nt][2], h1[nt][2], fmaf(h1[nt][3], h1[nt][3], sq1));
            }
            s0 = qreduce(s0); sq0 = qreduce(sq0);
            s1 = qreduce(s1); sq1 = qreduce(sq1);
            float mu0 = s0 * (1.f / 128.f);
            float rs0 = rsqrtf(sq0 * (1.f / 128.f) - mu0 * mu0 + EPSf);
            float mu1 = s1 * (1.f / 128.f);
            float rs1 = rsqrtf(sq1 * (1.f / 128.f) - mu1 * mu1 + EPSf);
#pragma unroll
            for (int nt = 0; nt < 8; nt++) {
                const int colb4 = (nt << 4) + 4 * t;
                float4 w  = *(const float4 *)(pf + 256 + colb4);
                float4 bb = *(const float4 *)(pf + 384 + colb4);
                h1[nt][0]   = fmaf((h1[nt][0]   - mu0) * rs0, w.x, bb.x);
                h1[nt][1]   = fmaf((h1[nt][1]   - mu0) * rs0, w.y, bb.y);
                h1[nt+8][0] = fmaf((h1[nt+8][0] - mu0) * rs0, w.z, bb.z);
                h1[nt+8][1] = fmaf((h1[nt+8][1] - mu0) * rs0, w.w, bb.w);
                h1[nt][2]   = fmaf((h1[nt][2]   - mu1) * rs1, w.x, bb.x);
                h1[nt][3]   = fmaf((h1[nt][3]   - mu1) * rs1, w.y, bb.y);
                h1[nt+8][2] = fmaf((h1[nt+8][2] - mu1) * rs1, w.z, bb.z);
                h1[nt+8][3] = fmaf((h1[nt+8][3] - mu1) * rs1, w.w, bb.w);
            }
        }
        // repack ln2(h1) -> pi-ordered fp16 A frags (K=128)
        u32 ah2[32], al2[32];
#pragma unroll
        for (int kt = 0; kt < 8; kt++) {
            split2h(h1[kt][0],   h1[kt][1],   ah2[4*kt+0], al2[4*kt+0]);
            split2h(h1[kt][2],   h1[kt][3],   ah2[4*kt+1], al2[4*kt+1]);
            split2h(h1[kt+8][0], h1[kt+8][1], ah2[4*kt+2], al2[4*kt+2]);
            split2h(h1[kt+8][2], h1[kt+8][3], ah2[4*kt+3], al2[4*kt+3]);
        }

        // ---------- GEMM5: out = ln2h1 @ W2^T + b2 (sigma rows; float4 stores, 2-pass) ----------
        float co[8][4];
#pragma unroll
        for (int i = 0; i < 8; i++) { co[i][0]=0.f; co[i][1]=0.f; co[i][2]=0.f; co[i][3]=0.f; }
        do_gemm_h<8, 8>(co, ah2, al2, BW2, lane);

#pragma unroll
        for (int nt = 0; nt < 4; nt++) {
            const int colb4 = (nt << 4) + 4 * t;
            float4 b4 = *(const float4 *)(pf + 192 + colb4);
            float4 oA, oB;
            oA.x = co[nt][0]   + b4.x; oA.y = co[nt][1]   + b4.y;
            oA.z = co[nt+4][0] + b4.z; oA.w = co[nt+4][1] + b4.w;
            oB.x = co[nt][2]   + b4.x; oB.y = co[nt][3]   + b4.y;
            oB.z = co[nt+4][2] + b4.z; oB.w = co[nt+4][3] + b4.w;
            *(float4 *)(OUT + q0 + colb4) = oA;
            *(float4 *)(OUT + q1 + colb4) = oB;
        }
    }
}

extern "C" void kernel_launch(void* const* d_in, const int* in_sizes, int n_in,
                              void* d_out, int out_size) {
    const float* Qin  = (const float*)d_in[0];
    const float* Kin  = (const float*)d_in[1];
    const float* Vin  = (const float*)d_in[2];
    const float* MEM  = (const float*)d_in[3];
    const float* Wq   = (const float*)d_in[4];
    const float* Wk   = (const float*)d_in[5];
    const float* Wv   = (const float*)d_in[6];
    const float* FG   = (const float*)d_in[7];
    const float* LN1W = (const float*)d_in[8];
    const float* LN1B = (const float*)d_in[9];
    const float* W1   = (const float*)d_in[10];
    const float* LN2W = (const float*)d_in[11];
    const float* LN2B = (const float*)d_in[12];
    const float* W2   = (const float*)d_in[13];
    const float* B2   = (const float*)d_in[14];

    float* OUT = (float*)d_out;                       // [B,S,HID]
    float* CM  = OUT + (size_t)B_ * S_ * H_ * 64;     // [B,H,S,D]

    static int attr_set = 0;
    if (!attr_set) {
        cudaFuncSetAttribute(mhba_hmma_kernel,
                             cudaFuncAttributeMaxDynamicSharedMemorySize, SMEM_TOTAL);
        attr_set = 1;
    }

    mhba_hmma_kernel<<<GRID, TPB, SMEM_TOTAL>>>(
        Qin, Kin, Vin, MEM, Wq, Wk, Wv, FG,
        LN1W, LN1B, W1, LN2W, LN2B, W2, B2, OUT, CM);
}

// round 14
// speedup vs baseline: 1.2467x; 1.1686x over previous
#include <cuda_runtime.h>
#include <cuda_fp16.h>
#include <cstdint>

#define B_    8
#define S_    4096
#define H_    16
#define NTILES 2048      // (B*H*S)/256
#define TPB   512        // 16 warps, each warp owns 16 rows of the 256-row tile
#define NWARP 16
#define GRID  148
#define EPSf  1e-5f

typedef uint32_t u32;
typedef uint64_t u64;

// ---------------- SMEM layout (bytes) ----------------
// All GEMMs fp16 1-pass: B fragments uint2 {b0h,b1h} per position per lane
#define OFF_WK   0            // 32 pos * 32 lanes * 8B = 8192
#define OFF_WV   8192
#define OFF_WQ   16384
#define OFF_W1   24576        // 64 pos = 16384
#define OFF_W2   40960        // 64 pos = 16384
#define OFF_PRM  57344        // fg[64], l1w[64], l1b[64], b2[64], l2w[128], l2b[128]
#define SMEM_TOTAL (57344 + 512 * 4)

// K-permutation pi (all GEMMs): physical k 16kt+2t+j / 16kt+2t+8+j hold logical
// cols 16kt+4t+j / 16kt+4t+2+j.
// N-perm sigma (G1,G2,G3,G5; N=64):  acc(nt, c0/c1) = logical cols 16(nt&3)+4t+2(nt>>2)+{0,1}
// N-perm sigma2 (G4; N=128):          acc(nt, c0/c1) = logical cols 16(nt&7)+4t+2(nt>>3)+{0,1}
// Precision: ALL GEMMs pure fp16 inputs (rn-rounded), fp32 accumulate.

// fp16 round pack
__device__ __forceinline__ u32 pack2h(float e, float o) {
    u32 h; asm("cvt.rn.f16x2.f32 %0, %1, %2;" : "=r"(h) : "f"(o), "f"(e));
    return h;
}

__device__ __forceinline__ void mma16816h(float *c, const u32 *a, u32 b0, u32 b1) {
    asm volatile("mma.sync.aligned.m16n8k16.row.col.f32.f16.f16.f32 "
                 "{%0,%1,%2,%3}, {%4,%5,%6,%7}, {%8,%9}, {%0,%1,%2,%3};"
                 : "+f"(c[0]), "+f"(c[1]), "+f"(c[2]), "+f"(c[3])
                 : "r"(a[0]), "r"(a[1]), "r"(a[2]), "r"(a[3]), "r"(b0), "r"(b1));
}

// fp16 1-pass GEMM
template<int NT, int KT>
__device__ __forceinline__ void do_gemm_h1(float (*c)[4], const u32 *ah,
                                           const uint2 *Bsm, int lane) {
#pragma unroll
    for (int kt = 0; kt < KT; kt++) {
#pragma unroll
        for (int nt = 0; nt < NT; nt++) {
            const int m = nt * KT + kt;
            uint2 p = Bsm[m * 32 + lane];
            mma16816h(c[nt], ah + 4*kt, p.x, p.y);
        }
    }
}

// Row index under N-permutation (sigma for NT==8, sigma2 for NT==16)
__device__ __forceinline__ int permrow(int nt, int g, int NT, bool perm) {
    if (!perm) return nt * 8 + g;
    int mask = (NT == 8) ? 3 : 7;
    int hi   = (NT == 8) ? (nt >> 2) : (nt >> 3);
    return ((nt & mask) << 4) + ((g >> 1) << 2) + (hi << 1) + (g & 1);
}

// Stage fp16-hi B fragments (uint2), K read through pi
template<bool PERM>
__device__ __forceinline__ void stageBh(uint2 *dst, const float * __restrict__ W,
                                        int NT, int KT, int K, int wid, int lane) {
    const int g = lane >> 2, t = lane & 3;
#pragma unroll 1
    for (int m = wid; m < NT * KT; m += NWARP) {
        int nt = m / KT, kt = m - nt * KT;
        int row = permrow(nt, g, NT, PERM);
        float4 wv = *(const float4 *)(W + row * K + kt * 16 + 4 * t);
        uint2 v = { pack2h(wv.x, wv.y), pack2h(wv.z, wv.w) };
        dst[m * 32 + lane] = v;
    }
}

// A kt-step load under pi, fp16 round-only
__device__ __forceinline__ void loadA_kt_h1(const float * __restrict__ r0,
                                            const float * __restrict__ r1,
                                            int t, u32 *ah) {
    float4 w0 = *(const float4 *)(r0 + 4 * t);
    float4 w1 = *(const float4 *)(r1 + 4 * t);
    ah[0] = pack2h(w0.x, w0.y);
    ah[1] = pack2h(w1.x, w1.y);
    ah[2] = pack2h(w0.z, w0.w);
    ah[3] = pack2h(w1.z, w1.w);
}

__device__ __forceinline__ float qreduce(float v) {
    v += __shfl_xor_sync(0xffffffffu, v, 1);
    v += __shfl_xor_sync(0xffffffffu, v, 2);
    return v;
}

__device__ __forceinline__ int qoff_of(int row) {
    int s = row & (S_ - 1);
    int h = (row >> 12) & (H_ - 1);
    int b = row >> 16;
    return (((b << 12) | s) << 10) + (h << 6);
}

__device__ __forceinline__ float gatef(float fg, float m, float kp, float vp) {
    float fgm  = fg * m;
    float cell = fmaf(kp, vp, fgm);
    return fmaf(1.f - fg, cell, fgm);
}

extern __shared__ char smem[];

__global__ void __launch_bounds__(TPB, 1) mhba_hmma_kernel(
    const float* __restrict__ Qin, const float* __restrict__ Kin,
    const float* __restrict__ Vin, const float* __restrict__ MEM,
    const float* __restrict__ Wq,  const float* __restrict__ Wk,
    const float* __restrict__ Wv,  const float* __restrict__ FG,
    const float* __restrict__ LN1W, const float* __restrict__ LN1B,
    const float* __restrict__ W1,
    const float* __restrict__ LN2W, const float* __restrict__ LN2B,
    const float* __restrict__ W2,  const float* __restrict__ B2,
    float* __restrict__ OUT, float* __restrict__ CM)
{
    const int tid  = threadIdx.x;
    const int wid  = tid >> 5;
    const int lane = tid & 31;
    const int g = lane >> 2, t = lane & 3;

    float *pf = (float *)(smem + OFF_PRM);
    if (tid < 64) {
        pf[tid]       = FG[tid];
        pf[64 + tid]  = LN1W[tid];
        pf[128 + tid] = LN1B[tid];
        pf[192 + tid] = B2[tid];
    }
    if (tid < 128) {
        pf[256 + tid] = LN2W[tid];
        pf[384 + tid] = LN2B[tid];
    }
    stageBh<true>((uint2 *)(smem + OFF_WK), Wk, 8,  4, 64,  wid, lane);
    stageBh<true>((uint2 *)(smem + OFF_WV), Wv, 8,  4, 64,  wid, lane);
    stageBh<true>((uint2 *)(smem + OFF_WQ), Wq, 8,  4, 64,  wid, lane);
    stageBh<true>((uint2 *)(smem + OFF_W1), W1, 16, 4, 64,  wid, lane);
    stageBh<true>((uint2 *)(smem + OFF_W2), W2, 8,  8, 128, wid, lane);
    __syncthreads();

    const uint2 *BWk = (const uint2 *)(smem + OFF_WK);
    const uint2 *BWv = (const uint2 *)(smem + OFF_WV);
    const uint2 *BWq = (const uint2 *)(smem + OFF_WQ);
    const uint2 *BW1 = (const uint2 *)(smem + OFF_W1);
    const uint2 *BW2 = (const uint2 *)(smem + OFF_W2);

#pragma unroll 1
    for (int tile = blockIdx.x; tile < NTILES; tile += gridDim.x) {
        const int rbase = tile * 256 + wid * 16;
        const int row0 = rbase + g;
        const int row1 = row0 + 8;
        const int q0 = qoff_of(row0), q1 = qoff_of(row1);
        const int m0 = row0 << 6,     m1 = row1 << 6;

        // ---------- front: K and V fragments up front (independent LDGs) ----------
        u32 kah[16], vah[16];
#pragma unroll
        for (int kt = 0; kt < 4; kt++)
            loadA_kt_h1(Kin + q0 + kt * 16, Kin + q1 + kt * 16, t, kah + 4 * kt);
#pragma unroll
        for (int kt = 0; kt < 4; kt++)
            loadA_kt_h1(Vin + q0 + kt * 16, Vin + q1 + kt * 16, t, vah + 4 * kt);

        // ---------- GEMM1: kp = Xk @ Wk^T ----------
        float ckp[8][4];
#pragma unroll
        for (int i = 0; i < 8; i++) { ckp[i][0]=0.f; ckp[i][1]=0.f; ckp[i][2]=0.f; ckp[i][3]=0.f; }
        do_gemm_h1<8, 4>(ckp, kah, BWk, lane);

        // issue MEM loads now; latency hides under GEMM2
        float4 mmA[4], mmB[4];
#pragma unroll
        for (int nt = 0; nt < 4; nt++) {
            const int colb4 = (nt << 4) + 4 * t;
            mmA[nt] = *(const float4 *)(MEM + m0 + colb4);
            mmB[nt] = *(const float4 *)(MEM + m1 + colb4);
        }

        // ---------- GEMM2: vp = Xv @ Wv^T ----------
        float cvp[8][4];
#pragma unroll
        for (int i = 0; i < 8; i++) { cvp[i][0]=0.f; cvp[i][1]=0.f; cvp[i][2]=0.f; cvp[i][3]=0.f; }
        do_gemm_h1<8, 4>(cvp, vah, BWv, lane);

        // ---------- gate -> cur_mem (float4 stores via nt/nt+4 pairing) ----------
#pragma unroll
        for (int nt = 0; nt < 4; nt++) {
            const int colb4 = (nt << 4) + 4 * t;
            float4 fg4 = *(const float4 *)(pf + colb4);
            float4 cA, cB;
            cA.x = gatef(fg4.x, mmA[nt].x, ckp[nt][0],   cvp[nt][0]);
            cA.y = gatef(fg4.y, mmA[nt].y, ckp[nt][1],   cvp[nt][1]);
            cA.z = gatef(fg4.z, mmA[nt].z, ckp[nt+4][0], cvp[nt+4][0]);
            cA.w = gatef(fg4.w, mmA[nt].w, ckp[nt+4][1], cvp[nt+4][1]);
            cB.x = gatef(fg4.x, mmB[nt].x, ckp[nt][2],   cvp[nt][2]);
            cB.y = gatef(fg4.y, mmB[nt].y, ckp[nt][3],   cvp[nt][3]);
            cB.z = gatef(fg4.z, mmB[nt].z, ckp[nt+4][2], cvp[nt+4][2]);
            cB.w = gatef(fg4.w, mmB[nt].w, ckp[nt+4][3], cvp[nt+4][3]);
            *(float4 *)(CM + m0 + colb4) = cA;
            *(float4 *)(CM + m1 + colb4) = cB;
            cvp[nt][0]   = cA.x; cvp[nt][1]   = cA.y;
            cvp[nt+4][0] = cA.z; cvp[nt+4][1] = cA.w;
            cvp[nt][2]   = cB.x; cvp[nt][3]   = cB.y;
            cvp[nt+4][2] = cB.z; cvp[nt+4][3] = cB.w;
        }

        // ---------- GEMM3: qp = Xq @ Wq^T ----------
        u32 ah[16];
#pragma unroll
        for (int kt = 0; kt < 4; kt++)
            loadA_kt_h1(Qin + q0 + kt * 16, Qin + q1 + kt * 16, t, ah + 4 * kt);
#pragma unroll
        for (int i = 0; i < 8; i++) { ckp[i][0]=0.f; ckp[i][1]=0.f; ckp[i][2]=0.f; ckp[i][3]=0.f; }
        do_gemm_h1<8, 4>(ckp, ah, BWq, lane);

        // ---------- cv = qp * cm ; LN1 (float4 param reads) ----------
#pragma unroll
        for (int nt = 0; nt < 8; nt++) {
            cvp[nt][0] *= ckp[nt][0]; cvp[nt][1] *= ckp[nt][1];
            cvp[nt][2] *= ckp[nt][2]; cvp[nt][3] *= ckp[nt][3];
        }
        {
            float s0 = 0.f, sq0 = 0.f, s1 = 0.f, sq1 = 0.f;
#pragma unroll
            for (int nt = 0; nt < 8; nt++) {
                s0 += cvp[nt][0] + cvp[nt][1];
                sq0 = fmaf(cvp[nt][0], cvp[nt][0], fmaf(cvp[nt][1], cvp[nt][1], sq0));
                s1 += cvp[nt][2] + cvp[nt][3];
                sq1 = fmaf(cvp[nt][2], cvp[nt][2], fmaf(cvp[nt][3], cvp[nt][3], sq1));
            }
            s0 = qreduce(s0); sq0 = qreduce(sq0);
            s1 = qreduce(s1); sq1 = qreduce(sq1);
            float mu0 = s0 * (1.f / 64.f);
            float rs0 = rsqrtf(sq0 * (1.f / 64.f) - mu0 * mu0 + EPSf);
            float mu1 = s1 * (1.f / 64.f);
            float rs1 = rsqrtf(sq1 * (1.f / 64.f) - mu1 * mu1 + EPSf);
#pragma unroll
            for (int nt = 0; nt < 4; nt++) {
                const int colb4 = (nt << 4) + 4 * t;
                float4 w  = *(const float4 *)(pf + 64 + colb4);
                float4 bb = *(const float4 *)(pf + 128 + colb4);
                cvp[nt][0]   = fmaf((cvp[nt][0]   - mu0) * rs0, w.x, bb.x);
                cvp[nt][1]   = fmaf((cvp[nt][1]   - mu0) * rs0, w.y, bb.y);
                cvp[nt+4][0] = fmaf((cvp[nt+4][0] - mu0) * rs0, w.z, bb.z);
                cvp[nt+4][1] = fmaf((cvp[nt+4][1] - mu0) * rs0, w.w, bb.w);
                cvp[nt][2]   = fmaf((cvp[nt][2]   - mu1) * rs1, w.x, bb.x);
                cvp[nt][3]   = fmaf((cvp[nt][3]   - mu1) * rs1, w.y, bb.y);
                cvp[nt+4][2] = fmaf((cvp[nt+4][2] - mu1) * rs1, w.z, bb.z);
                cvp[nt+4][3] = fmaf((cvp[nt+4][3] - mu1) * rs1, w.w, bb.w);
            }
        }
        // repack ln1(cv) -> pi-ordered fp16 A frags (K=64)
#pragma unroll
        for (int kt = 0; kt < 4; kt++) {
            ah[4*kt+0] = pack2h(cvp[kt][0],   cvp[kt][1]);
            ah[4*kt+1] = pack2h(cvp[kt][2],   cvp[kt][3]);
            ah[4*kt+2] = pack2h(cvp[kt+4][0], cvp[kt+4][1]);
            ah[4*kt+3] = pack2h(cvp[kt+4][2], cvp[kt+4][3]);
        }

        // ---------- GEMM4: h1 = ln1cv @ W1^T (N=128, sigma2 rows) ----------
        float h1[16][4];
#pragma unroll
        for (int i = 0; i < 16; i++) { h1[i][0]=0.f; h1[i][1]=0.f; h1[i][2]=0.f; h1[i][3]=0.f; }
        do_gemm_h1<16, 4>(h1, ah, BW1, lane);

        // ---------- LN2 (float4 params via nt/nt+8 pairing) ----------
        {
            float s0 = 0.f, sq0 = 0.f, s1 = 0.f, sq1 = 0.f;
#pragma unroll
            for (int nt = 0; nt < 16; nt++) {
                s0 += h1[nt][0] + h1[nt][1];
                sq0 = fmaf(h1[nt][0], h1[nt][0], fmaf(h1[nt][1], h1[nt][1], sq0));
                s1 += h1[nt][2] + h1[nt][3];
                sq1 = fmaf(h1[nt][2], h1[nt][2], fmaf(h1[nt][3], h1[nt][3], sq1));
            }
            s0 = qreduce(s0); sq0 = qreduce(sq0);
            s1 = qreduce(s1); sq1 = qreduce(sq1);
            float mu0 = s0 * (1.f / 128.f);
            float rs0 = rsqrtf(sq0 * (1.f / 128.f) - mu0 * mu0 + EPSf);
            float mu1 = s1 * (1.f / 128.f);
            float rs1 = rsqrtf(sq1 * (1.f / 128.f) - mu1 * mu1 + EPSf);
#pragma unroll
            for (int nt = 0; nt < 8; nt++) {
                const int colb4 = (nt << 4) + 4 * t;
                float4 w  = *(const float4 *)(pf + 256 + colb4);
                float4 bb = *(const float4 *)(pf + 384 + colb4);
                h1[nt][0]   = fmaf((h1[nt][0]   - mu0) * rs0, w.x, bb.x);
                h1[nt][1]   = fmaf((h1[nt][1]   - mu0) * rs0, w.y, bb.y);
                h1[nt+8][0] = fmaf((h1[nt+8][0] - mu0) * rs0, w.z, bb.z);
                h1[nt+8][1] = fmaf((h1[nt+8][1] - mu0) * rs0, w.w, bb.w);
                h1[nt][2]   = fmaf((h1[nt][2]   - mu1) * rs1, w.x, bb.x);
                h1[nt][3]   = fmaf((h1[nt][3]   - mu1) * rs1, w.y, bb.y);
                h1[nt+8][2] = fmaf((h1[nt+8][2] - mu1) * rs1, w.z, bb.z);
                h1[nt+8][3] = fmaf((h1[nt+8][3] - mu1) * rs1, w.w, bb.w);
            }
        }
        // repack ln2(h1) -> pi-ordered fp16 A frags (K=128)
        u32 ah2[32];
#pragma unroll
        for (int kt = 0; kt < 8; kt++) {
            ah2[4*kt+0] = pack2h(h1[kt][0],   h1[kt][1]);
            ah2[4*kt+1] = pack2h(h1[kt][2],   h1[kt][3]);
            ah2[4*kt+2] = pack2h(h1[kt+8][0], h1[kt+8][1]);
            ah2[4*kt+3] = pack2h(h1[kt+8][2], h1[kt+8][3]);
        }

        // ---------- GEMM5: out = ln2h1 @ W2^T + b2 (sigma rows; float4 stores) ----------
        float co[8][4];
#pragma unroll
        for (int i = 0; i < 8; i++) { co[i][0]=0.f; co[i][1]=0.f; co[i][2]=0.f; co[i][3]=0.f; }
        do_gemm_h1<8, 8>(co, ah2, BW2, lane);

#pragma unroll
        for (int nt = 0; nt < 4; nt++) {
            const int colb4 = (nt << 4) + 4 * t;
            float4 b4 = *(const float4 *)(pf + 192 + colb4);
            float4 oA, oB;
            oA.x = co[nt][0]   + b4.x; oA.y = co[nt][1]   + b4.y;
            oA.z = co[nt+4][0] + b4.z; oA.w = co[nt+4][1] + b4.w;
            oB.x = co[nt][2]   + b4.x; oB.y = co[nt][3]   + b4.y;
            oB.z = co[nt+4][2] + b4.z; oB.w = co[nt+4][3] + b4.w;
            *(float4 *)(OUT + q0 + colb4) = oA;
            *(float4 *)(OUT + q1 + colb4) = oB;
        }
    }
}

extern "C" void kernel_launch(void* const* d_in, const int* in_sizes, int n_in,
                              void* d_out, int out_size) {
    const float* Qin  = (const float*)d_in[0];
    const float* Kin  = (const float*)d_in[1];
    const float* Vin  = (const float*)d_in[2];
    const float* MEM  = (const float*)d_in[3];
    const float* Wq   = (const float*)d_in[4];
    const float* Wk   = (const float*)d_in[5];
    const float* Wv   = (const float*)d_in[6];
    const float* FG   = (const float*)d_in[7];
    const float* LN1W = (const float*)d_in[8];
    const float* LN1B = (const float*)d_in[9];
    const float* W1   = (const float*)d_in[10];
    const float* LN2W = (const float*)d_in[11];
    const float* LN2B = (const float*)d_in[12];
    const float* W2   = (const float*)d_in[13];
    const float* B2   = (const float*)d_in[14];

    float* OUT = (float*)d_out;                       // [B,S,HID]
    float* CM  = OUT + (size_t)B_ * S_ * H_ * 64;     // [B,H,S,D]

    static int attr_set = 0;
    if (!attr_set) {
        cudaFuncSetAttribute(mhba_hmma_kernel,
                             cudaFuncAttributeMaxDynamicSharedMemorySize, SMEM_TOTAL);
        attr_set = 1;
    }

    mhba_hmma_kernel<<<GRID, TPB, SMEM_TOTAL>>>(
        Qin, Kin, Vin, MEM, Wq, Wk, Wv, FG,
        LN1W, LN1B, W1, LN2W, LN2B, W2, B2, OUT, CM);
}

// round 15
// speedup vs baseline: 1.2830x; 1.0291x over previous
#include <cuda_runtime.h>
#include <cuda_fp16.h>
#include <cstdint>

#define B_    8
#define S_    4096
#define H_    16
#define NTILES 2048      // (B*H*S)/256
#define TPB   512        // 16 warps, each warp owns 16 rows of the 256-row tile
#define NWARP 16
#define GRID  148
#define EPSf  1e-5f

typedef uint32_t u32;
typedef uint64_t u64;

// ---------------- SMEM layout (bytes) ----------------
#define OFF_WK   0            // 32 pos * 32 lanes * 8B = 8192
#define OFF_WV   8192
#define OFF_WQ   16384
#define OFF_W1   24576        // 64 pos = 16384
#define OFF_W2   40960        // 64 pos = 16384
#define OFF_PRM  57344        // fg[64], l1w[64], l1b[64], b2[64], l2w[128], l2b[128]
#define SMEM_TOTAL (57344 + 512 * 4)

// pi/sigma/sigma2 permutations as in R9-R14. All GEMMs pure fp16, fp32 accum.

__device__ __forceinline__ u32 pack2h(float e, float o) {
    u32 h; asm("cvt.rn.f16x2.f32 %0, %1, %2;" : "=r"(h) : "f"(o), "f"(e));
    return h;
}

__device__ __forceinline__ void mma16816h(float *c, const u32 *a, u32 b0, u32 b1) {
    asm volatile("mma.sync.aligned.m16n8k16.row.col.f32.f16.f16.f32 "
                 "{%0,%1,%2,%3}, {%4,%5,%6,%7}, {%8,%9}, {%0,%1,%2,%3};"
                 : "+f"(c[0]), "+f"(c[1]), "+f"(c[2]), "+f"(c[3])
                 : "r"(a[0]), "r"(a[1]), "r"(a[2]), "r"(a[3]), "r"(b0), "r"(b1));
}

template<int NT, int KT>
__device__ __forceinline__ void do_gemm_h1(float (*c)[4], const u32 *ah,
                                           const uint2 *Bsm, int lane) {
#pragma unroll
    for (int kt = 0; kt < KT; kt++) {
#pragma unroll
        for (int nt = 0; nt < NT; nt++) {
            const int m = nt * KT + kt;
            uint2 p = Bsm[m * 32 + lane];
            mma16816h(c[nt], ah + 4*kt, p.x, p.y);
        }
    }
}

__device__ __forceinline__ int permrow(int nt, int g, int NT, bool perm) {
    if (!perm) return nt * 8 + g;
    int mask = (NT == 8) ? 3 : 7;
    int hi   = (NT == 8) ? (nt >> 2) : (nt >> 3);
    return ((nt & mask) << 4) + ((g >> 1) << 2) + (hi << 1) + (g & 1);
}

template<bool PERM>
__device__ __forceinline__ void stageBh(uint2 *dst, const float * __restrict__ W,
                                        int NT, int KT, int K, int wid, int lane) {
    const int g = lane >> 2, t = lane & 3;
#pragma unroll 1
    for (int m = wid; m < NT * KT; m += NWARP) {
        int nt = m / KT, kt = m - nt * KT;
        int row = permrow(nt, g, NT, PERM);
        float4 wv = *(const float4 *)(W + row * K + kt * 16 + 4 * t);
        uint2 v = { pack2h(wv.x, wv.y), pack2h(wv.z, wv.w) };
        dst[m * 32 + lane] = v;
    }
}

// A kt-step load under pi, fp16 round-only, streaming
__device__ __forceinline__ void loadA_kt_h1(const float * __restrict__ r0,
                                            const float * __restrict__ r1,
                                            int t, u32 *ah) {
    float4 w0 = __ldcs((const float4 *)(r0 + 4 * t));
    float4 w1 = __ldcs((const float4 *)(r1 + 4 * t));
    ah[0] = pack2h(w0.x, w0.y);
    ah[1] = pack2h(w1.x, w1.y);
    ah[2] = pack2h(w0.z, w0.w);
    ah[3] = pack2h(w1.z, w1.w);
}

__device__ __forceinline__ float qreduce(float v) {
    v += __shfl_xor_sync(0xffffffffu, v, 1);
    v += __shfl_xor_sync(0xffffffffu, v, 2);
    return v;
}

__device__ __forceinline__ int qoff_of(int row) {
    int s = row & (S_ - 1);
    int h = (row >> 12) & (H_ - 1);
    int b = row >> 16;
    return (((b << 12) | s) << 10) + (h << 6);
}

__device__ __forceinline__ float gatef(float fg, float m, float kp, float vp) {
    float fgm  = fg * m;
    float cell = fmaf(kp, vp, fgm);
    return fmaf(1.f - fg, cell, fgm);
}

extern __shared__ char smem[];

__global__ void __launch_bounds__(TPB, 1) mhba_hmma_kernel(
    const float* __restrict__ Qin, const float* __restrict__ Kin,
    const float* __restrict__ Vin, const float* __restrict__ MEM,
    const float* __restrict__ Wq,  const float* __restrict__ Wk,
    const float* __restrict__ Wv,  const float* __restrict__ FG,
    const float* __restrict__ LN1W, const float* __restrict__ LN1B,
    const float* __restrict__ W1,
    const float* __restrict__ LN2W, const float* __restrict__ LN2B,
    const float* __restrict__ W2,  const float* __restrict__ B2,
    float* __restrict__ OUT, float* __restrict__ CM)
{
    const int tid  = threadIdx.x;
    const int wid  = tid >> 5;
    const int lane = tid & 31;
    const int g = lane >> 2, t = lane & 3;

    float *pf = (float *)(smem + OFF_PRM);
    if (tid < 64) {
        pf[tid]       = FG[tid];
        pf[64 + tid]  = LN1W[tid];
        pf[128 + tid] = LN1B[tid];
        pf[192 + tid] = B2[tid];
    }
    if (tid < 128) {
        pf[256 + tid] = LN2W[tid];
        pf[384 + tid] = LN2B[tid];
    }
    stageBh<true>((uint2 *)(smem + OFF_WK), Wk, 8,  4, 64,  wid, lane);
    stageBh<true>((uint2 *)(smem + OFF_WV), Wv, 8,  4, 64,  wid, lane);
    stageBh<true>((uint2 *)(smem + OFF_WQ), Wq, 8,  4, 64,  wid, lane);
    stageBh<true>((uint2 *)(smem + OFF_W1), W1, 16, 4, 64,  wid, lane);
    stageBh<true>((uint2 *)(smem + OFF_W2), W2, 8,  8, 128, wid, lane);
    __syncthreads();

    const uint2 *BWk = (const uint2 *)(smem + OFF_WK);
    const uint2 *BWv = (const uint2 *)(smem + OFF_WV);
    const uint2 *BWq = (const uint2 *)(smem + OFF_WQ);
    const uint2 *BW1 = (const uint2 *)(smem + OFF_W1);
    const uint2 *BW2 = (const uint2 *)(smem + OFF_W2);

    // ---- preload tile 0's K/V fragments ----
    u32 kah[16], vah[16];
    {
        const int rbase = blockIdx.x * 256 + wid * 16;
        const int r0 = rbase + g, r1 = r0 + 8;
        const int qa = qoff_of(r0), qb = qoff_of(r1);
#pragma unroll
        for (int kt = 0; kt < 4; kt++) {
            loadA_kt_h1(Kin + qa + kt * 16, Kin + qb + kt * 16, t, kah + 4 * kt);
            loadA_kt_h1(Vin + qa + kt * 16, Vin + qb + kt * 16, t, vah + 4 * kt);
        }
    }

#pragma unroll 1
    for (int tile = blockIdx.x; tile < NTILES; tile += gridDim.x) {
        const int rbase = tile * 256 + wid * 16;
        const int row0 = rbase + g;
        const int row1 = row0 + 8;
        const int q0 = qoff_of(row0), q1 = qoff_of(row1);
        const int m0 = row0 << 6,     m1 = row1 << 6;

        // ---------- GEMM1: kp = Xk @ Wk^T ----------
        float ckp[8][4];
#pragma unroll
        for (int i = 0; i < 8; i++) { ckp[i][0]=0.f; ckp[i][1]=0.f; ckp[i][2]=0.f; ckp[i][3]=0.f; }
        do_gemm_h1<8, 4>(ckp, kah, BWk, lane);

        // MEM loads: latency hides under GEMM2
        float4 mmA[4], mmB[4];
#pragma unroll
        for (int nt = 0; nt < 4; nt++) {
            const int colb4 = (nt << 4) + 4 * t;
            mmA[nt] = __ldcs((const float4 *)(MEM + m0 + colb4));
            mmB[nt] = __ldcs((const float4 *)(MEM + m1 + colb4));
        }

        // ---------- GEMM2: vp = Xv @ Wv^T ----------
        float cvp[8][4];
#pragma unroll
        for (int i = 0; i < 8; i++) { cvp[i][0]=0.f; cvp[i][1]=0.f; cvp[i][2]=0.f; cvp[i][3]=0.f; }
        do_gemm_h1<8, 4>(cvp, vah, BWv, lane);

        // Q fragment loads BEFORE gate: gate ALU covers part of the latency
        u32 ah[16];
#pragma unroll
        for (int kt = 0; kt < 4; kt++)
            loadA_kt_h1(Qin + q0 + kt * 16, Qin + q1 + kt * 16, t, ah + 4 * kt);

        // ---------- gate -> cur_mem (float4 streaming stores) ----------
#pragma unroll
        for (int nt = 0; nt < 4; nt++) {
            const int colb4 = (nt << 4) + 4 * t;
            float4 fg4 = *(const float4 *)(pf + colb4);
            float4 cA, cB;
            cA.x = gatef(fg4.x, mmA[nt].x, ckp[nt][0],   cvp[nt][0]);
            cA.y = gatef(fg4.y, mmA[nt].y, ckp[nt][1],   cvp[nt][1]);
            cA.z = gatef(fg4.z, mmA[nt].z, ckp[nt+4][0], cvp[nt+4][0]);
            cA.w = gatef(fg4.w, mmA[nt].w, ckp[nt+4][1], cvp[nt+4][1]);
            cB.x = gatef(fg4.x, mmB[nt].x, ckp[nt][2],   cvp[nt][2]);
            cB.y = gatef(fg4.y, mmB[nt].y, ckp[nt][3],   cvp[nt][3]);
            cB.z = gatef(fg4.z, mmB[nt].z, ckp[nt+4][2], cvp[nt+4][2]);
            cB.w = gatef(fg4.w, mmB[nt].w, ckp[nt+4][3], cvp[nt+4][3]);
            __stcs((float4 *)(CM + m0 + colb4), cA);
            __stcs((float4 *)(CM + m1 + colb4), cB);
            cvp[nt][0]   = cA.x; cvp[nt][1]   = cA.y;
            cvp[nt+4][0] = cA.z; cvp[nt+4][1] = cA.w;
            cvp[nt][2]   = cB.x; cvp[nt][3]   = cB.y;
            cvp[nt+4][2] = cB.z; cvp[nt+4][3] = cB.w;
        }

        // ---------- GEMM3: qp = Xq @ Wq^T ----------
#pragma unroll
        for (int i = 0; i < 8; i++) { ckp[i][0]=0.f; ckp[i][1]=0.f; ckp[i][2]=0.f; ckp[i][3]=0.f; }
        do_gemm_h1<8, 4>(ckp, ah, BWq, lane);

        // ---------- cv = qp * cm ; LN1 ----------
#pragma unroll
        for (int nt = 0; nt < 8; nt++) {
            cvp[nt][0] *= ckp[nt][0]; cvp[nt][1] *= ckp[nt][1];
            cvp[nt][2] *= ckp[nt][2]; cvp[nt][3] *= ckp[nt][3];
        }
        {
            float s0 = 0.f, sq0 = 0.f, s1 = 0.f, sq1 = 0.f;
#pragma unroll
            for (int nt = 0; nt < 8; nt++) {
                s0 += cvp[nt][0] + cvp[nt][1];
                sq0 = fmaf(cvp[nt][0], cvp[nt][0], fmaf(cvp[nt][1], cvp[nt][1], sq0));
                s1 += cvp[nt][2] + cvp[nt][3];
                sq1 = fmaf(cvp[nt][2], cvp[nt][2], fmaf(cvp[nt][3], cvp[nt][3], sq1));
            }
            s0 = qreduce(s0); sq0 = qreduce(sq0);
            s1 = qreduce(s1); sq1 = qreduce(sq1);
            float mu0 = s0 * (1.f / 64.f);
            float rs0 = rsqrtf(sq0 * (1.f / 64.f) - mu0 * mu0 + EPSf);
            float mu1 = s1 * (1.f / 64.f);
            float rs1 = rsqrtf(sq1 * (1.f / 64.f) - mu1 * mu1 + EPSf);
#pragma unroll
            for (int nt = 0; nt < 4; nt++) {
                const int colb4 = (nt << 4) + 4 * t;
                float4 w  = *(const float4 *)(pf + 64 + colb4);
                float4 bb = *(const float4 *)(pf + 128 + colb4);
                cvp[nt][0]   = fmaf((cvp[nt][0]   - mu0) * rs0, w.x, bb.x);
                cvp[nt][1]   = fmaf((cvp[nt][1]   - mu0) * rs0, w.y, bb.y);
                cvp[nt+4][0] = fmaf((cvp[nt+4][0] - mu0) * rs0, w.z, bb.z);
                cvp[nt+4][1] = fmaf((cvp[nt+4][1] - mu0) * rs0, w.w, bb.w);
                cvp[nt][2]   = fmaf((cvp[nt][2]   - mu1) * rs1, w.x, bb.x);
                cvp[nt][3]   = fmaf((cvp[nt][3]   - mu1) * rs1, w.y, bb.y);
                cvp[nt+4][2] = fmaf((cvp[nt+4][2] - mu1) * rs1, w.z, bb.z);
                cvp[nt+4][3] = fmaf((cvp[nt+4][3] - mu1) * rs1, w.w, bb.w);
            }
        }
        // repack ln1(cv) -> pi-ordered fp16 A frags (K=64)
#pragma unroll
        for (int kt = 0; kt < 4; kt++) {
            ah[4*kt+0] = pack2h(cvp[kt][0],   cvp[kt][1]);
            ah[4*kt+1] = pack2h(cvp[kt][2],   cvp[kt][3]);
            ah[4*kt+2] = pack2h(cvp[kt+4][0], cvp[kt+4][1]);
            ah[4*kt+3] = pack2h(cvp[kt+4][2], cvp[kt+4][3]);
        }

        // ---------- GEMM4: h1 = ln1cv @ W1^T (N=128, sigma2 rows) ----------
        float h1[16][4];
#pragma unroll
        for (int i = 0; i < 16; i++) { h1[i][0]=0.f; h1[i][1]=0.f; h1[i][2]=0.f; h1[i][3]=0.f; }
        do_gemm_h1<16, 4>(h1, ah, BW1, lane);

        // ---------- LN2 ----------
        {
            float s0 = 0.f, sq0 = 0.f, s1 = 0.f, sq1 = 0.f;
#pragma unroll
            for (int nt = 0; nt < 16; nt++) {
                s0 += h1[nt][0] + h1[nt][1];
                sq0 = fmaf(h1[nt][0], h1[nt][0], fmaf(h1[nt][1], h1[nt][1], sq0));
                s1 += h1[nt][2] + h1[nt][3];
                sq1 = fmaf(h1[nt][2], h1[nt][2], fmaf(h1[nt][3], h1[nt][3], sq1));
            }
            s0 = qreduce(s0); sq0 = qreduce(sq0);
            s1 = qreduce(s1); sq1 = qreduce(sq1);
            float mu0 = s0 * (1.f / 128.f);
            float rs0 = rsqrtf(sq0 * (1.f / 128.f) - mu0 * mu0 + EPSf);
            float mu1 = s1 * (1.f / 128.f);
            float rs1 = rsqrtf(sq1 * (1.f / 128.f) - mu1 * mu1 + EPSf);
#pragma unroll
            for (int nt = 0; nt < 8; nt++) {
                const int colb4 = (nt << 4) + 4 * t;
                float4 w  = *(const float4 *)(pf + 256 + colb4);
                float4 bb = *(const float4 *)(pf + 384 + colb4);
                h1[nt][0]   = fmaf((h1[nt][0]   - mu0) * rs0, w.x, bb.x);
                h1[nt][1]   = fmaf((h1[nt][1]   - mu0) * rs0, w.y, bb.y);
                h1[nt+8][0] = fmaf((h1[nt+8][0] - mu0) * rs0, w.z, bb.z);
                h1[nt+8][1] = fmaf((h1[nt+8][1] - mu0) * rs0, w.w, bb.w);
                h1[nt][2]   = fmaf((h1[nt][2]   - mu1) * rs1, w.x, bb.x);
                h1[nt][3]   = fmaf((h1[nt][3]   - mu1) * rs1, w.y, bb.y);
                h1[nt+8][2] = fmaf((h1[nt+8][2] - mu1) * rs1, w.z, bb.z);
                h1[nt+8][3] = fmaf((h1[nt+8][3] - mu1) * rs1, w.w, bb.w);
            }
        }
        // repack ln2(h1) -> pi-ordered fp16 A frags (K=128)
        u32 ah2[32];
#pragma unroll
        for (int kt = 0; kt < 8; kt++) {
            ah2[4*kt+0] = pack2h(h1[kt][0],   h1[kt][1]);
            ah2[4*kt+1] = pack2h(h1[kt][2],   h1[kt][3]);
            ah2[4*kt+2] = pack2h(h1[kt+8][0], h1[kt+8][1]);
            ah2[4*kt+3] = pack2h(h1[kt+8][2], h1[kt+8][3]);
        }

        // ---------- prefetch next tile's K/V fragments (hidden under GEMM5) ----------
        {
            int tn = tile + gridDim.x;
            if (tn >= NTILES) tn = tile;          // clamp: harmless re-load on last iter
            const int rb = tn * 256 + wid * 16;
            const int r0n = rb + g, r1n = r0n + 8;
            const int qa = qoff_of(r0n), qb = qoff_of(r1n);
#pragma unroll
            for (int kt = 0; kt < 4; kt++) {
                loadA_kt_h1(Kin + qa + kt * 16, Kin + qb + kt * 16, t, kah + 4 * kt);
                loadA_kt_h1(Vin + qa + kt * 16, Vin + qb + kt * 16, t, vah + 4 * kt);
            }
        }

        // ---------- GEMM5: out = ln2h1 @ W2^T + b2 (sigma rows; streaming stores) ----------
        float co[8][4];
#pragma unroll
        for (int i = 0; i < 8; i++) { co[i][0]=0.f; co[i][1]=0.f; co[i][2]=0.f; co[i][3]=0.f; }
        do_gemm_h1<8, 8>(co, ah2, BW2, lane);

#pragma unroll
        for (int nt = 0; nt < 4; nt++) {
            const int colb4 = (nt << 4) + 4 * t;
            float4 b4 = *(const float4 *)(pf + 192 + colb4);
            float4 oA, oB;
            oA.x = co[nt][0]   + b4.x; oA.y = co[nt][1]   + b4.y;
            oA.z = co[nt+4][0] + b4.z; oA.w = co[nt+4][1] + b4.w;
            oB.x = co[nt][2]   + b4.x; oB.y = co[nt][3]   + b4.y;
            oB.z = co[nt+4][2] + b4.z; oB.w = co[nt+4][3] + b4.w;
            __stcs((float4 *)(OUT + q0 + colb4), oA);
            __stcs((float4 *)(OUT + q1 + colb4), oB);
        }
    }
}

extern "C" void kernel_launch(void* const* d_in, const int* in_sizes, int n_in,
                              void* d_out, int out_size) {
    const float* Qin  = (const float*)d_in[0];
    const float* Kin  = (const float*)d_in[1];
    const float* Vin  = (const float*)d_in[2];
    const float* MEM  = (const float*)d_in[3];
    const float* Wq   = (const float*)d_in[4];
    const float* Wk   = (const float*)d_in[5];
    const float* Wv   = (const float*)d_in[6];
    const float* FG   = (const float*)d_in[7];
    const float* LN1W = (const float*)d_in[8];
    const float* LN1B = (const float*)d_in[9];
    const float* W1   = (const float*)d_in[10];
    const float* LN2W = (const float*)d_in[11];
    const float* LN2B = (const float*)d_in[12];
    const float* W2   = (const float*)d_in[13];
    const float* B2   = (const float*)d_in[14];

    float* OUT = (float*)d_out;                       // [B,S,HID]
    float* CM  = OUT + (size_t)B_ * S_ * H_ * 64;     // [B,H,S,D]

    static int attr_set = 0;
    if (!attr_set) {
        cudaFuncSetAttribute(mhba_hmma_kernel,
                             cudaFuncAttributeMaxDynamicSharedMemorySize, SMEM_TOTAL);
        attr_set = 1;
    }

    mhba_hmma_kernel<<<GRID, TPB, SMEM_TOTAL>>>(
        Qin, Kin, Vin, MEM, Wq, Wk, Wv, FG,
        LN1W, LN1B, W1, LN2W, LN2B, W2, B2, OUT, CM);
}